// round 7
// baseline (speedup 1.0000x reference)
#include <cuda_runtime.h>
#include <cstdint>

// sbvr decode:
//   out[g*16 + l] = sum_s coeff_cache[coeff_idx[g]][s] * ((bvr[g][s] >> l) & 1)
// G = 4,194,304 groups, S = 4, L = 16.
//
// R6 -> R7: L1 data path is the ceiling (gather replays ~= 17 of ~22 L1
// cyc/warp-iter; 40us of L1-busy in a 58us kernel). Changes:
//  * register diet (rolling scalars, PF idx=2 / bvr=1, masks inside asm)
//    + __launch_bounds__(256,7): 48 -> 56 warp cap to fill L1 bubbles
//  * __ldcg gather: skip L1 allocation (most gathers miss the 228KB L1
//    anyway; table is 1MB) -> no fill/tag bank work
// Block-contiguous tiling and pipe-balanced decode unchanged.

static constexpr unsigned QT_TOTAL = 16u * 1024u * 1024u;  // 4M groups * 4 quarters
static constexpr int      BLOCK    = 256;
static constexpr int      ITER     = 8;                    // quarter-groups per thread
static constexpr unsigned BLOCKS   = QT_TOTAL / (BLOCK * ITER);  // 8192
static constexpr int      GSTRIDE  = BLOCK / 4;            // 64 groups per iteration

// Pipe-balanced decode: lop3 with predicate output (ALU; AND+test in one op)
// feeding predicated add.f32 (FMA pipe). Masks derived from m0 inside the asm
// (3 shl/call) to keep them out of the register file. Exact fp32 -> rel_err 0.
__device__ __forceinline__ float4 decode_quarter(int4 w, float4 c, unsigned m0)
{
    float4 r;
    asm(
    "{\n\t"
    ".reg .pred q, p0, p1, p2, p3;\n\t"
    ".reg .b32  t, m1, m2, m3;\n\t"
    "setp.ne.u32 q, %4, %4;\n\t"
    "shl.b32 m1, %8, 1;\n\t"
    "shl.b32 m2, %8, 2;\n\t"
    "shl.b32 m3, %8, 3;\n\t"
    // ---- element 0 ----
    "lop3.or.b32 t|p0, %4, %8, %4, 0xC0, q;\n\t"
    "lop3.or.b32 t|p1, %5, %8, %5, 0xC0, q;\n\t"
    "lop3.or.b32 t|p2, %6, %8, %6, 0xC0, q;\n\t"
    "lop3.or.b32 t|p3, %7, %8, %7, 0xC0, q;\n\t"
    "selp.f32 %0, %9, 0f00000000, p0;\n\t"
    "@p1 add.rn.f32 %0, %0, %10;\n\t"
    "@p2 add.rn.f32 %0, %0, %11;\n\t"
    "@p3 add.rn.f32 %0, %0, %12;\n\t"
    // ---- element 1 ----
    "lop3.or.b32 t|p0, %4, m1, %4, 0xC0, q;\n\t"
    "lop3.or.b32 t|p1, %5, m1, %5, 0xC0, q;\n\t"
    "lop3.or.b32 t|p2, %6, m1, %6, 0xC0, q;\n\t"
    "lop3.or.b32 t|p3, %7, m1, %7, 0xC0, q;\n\t"
    "selp.f32 %1, %9, 0f00000000, p0;\n\t"
    "@p1 add.rn.f32 %1, %1, %10;\n\t"
    "@p2 add.rn.f32 %1, %1, %11;\n\t"
    "@p3 add.rn.f32 %1, %1, %12;\n\t"
    // ---- element 2 ----
    "lop3.or.b32 t|p0, %4, m2, %4, 0xC0, q;\n\t"
    "lop3.or.b32 t|p1, %5, m2, %5, 0xC0, q;\n\t"
    "lop3.or.b32 t|p2, %6, m2, %6, 0xC0, q;\n\t"
    "lop3.or.b32 t|p3, %7, m2, %7, 0xC0, q;\n\t"
    "selp.f32 %2, %9, 0f00000000, p0;\n\t"
    "@p1 add.rn.f32 %2, %2, %10;\n\t"
    "@p2 add.rn.f32 %2, %2, %11;\n\t"
    "@p3 add.rn.f32 %2, %2, %12;\n\t"
    // ---- element 3 ----
    "lop3.or.b32 t|p0, %4, m3, %4, 0xC0, q;\n\t"
    "lop3.or.b32 t|p1, %5, m3, %5, 0xC0, q;\n\t"
    "lop3.or.b32 t|p2, %6, m3, %6, 0xC0, q;\n\t"
    "lop3.or.b32 t|p3, %7, m3, %7, 0xC0, q;\n\t"
    "selp.f32 %3, %9, 0f00000000, p0;\n\t"
    "@p1 add.rn.f32 %3, %3, %10;\n\t"
    "@p2 add.rn.f32 %3, %3, %11;\n\t"
    "@p3 add.rn.f32 %3, %3, %12;\n\t"
    "}\n\t"
    : "=f"(r.x), "=f"(r.y), "=f"(r.z), "=f"(r.w)
    : "r"(w.x), "r"(w.y), "r"(w.z), "r"(w.w),
      "r"(m0),
      "f"(c.x), "f"(c.y), "f"(c.z), "f"(c.w));
    return r;
}

__global__ __launch_bounds__(BLOCK, 7) void sbvr_kernel(
    const float4* __restrict__ coeff_cache,   // [65536] rows of 4 floats
    const int*    __restrict__ coeff_idx,     // [G]
    const int4*   __restrict__ bvr,           // [G]
    float4*       __restrict__ out)           // [4*G]
{
    // Block-contiguous tile: quarter-indices [b*BLOCK*ITER, ...), iteration i
    // at +i*BLOCK. All per-iteration offsets are small immediates.
    unsigned t = blockIdx.x * (unsigned)(BLOCK * ITER) + threadIdx.x;
    unsigned g = t >> 2;

    const int*  ip = coeff_idx + g;
    const int4* wp = bvr + g;
    float4*     op = out + t;

    unsigned m0 = 1u << ((t & 3u) * 4u);   // BLOCK % 4 == 0: invariant over i

    // Rolling pipeline scalars (no arrays -> minimal registers):
    //   idx prefetch distance 2 (decouples gather from idx latency),
    //   bvr distance 1, gather distance 1.
    int    ci1 = __ldcs(ip);               // idx for iter 0
    int    ci2 = __ldcs(ip + GSTRIDE);     // idx for iter 1
    int4   w0  = __ldcs(wp);               // bvr for iter 0
    float4 c_cur = __ldcg(coeff_cache + ci1);  // gather for iter 0

    #pragma unroll
    for (int i = 0; i < ITER; i++) {
        int ci_next = ci2;
        if (i + 2 < ITER)                   // idx for iter i+2
            ci2 = __ldcs(ip + (i + 2) * GSTRIDE);

        int4 w1 = w0;
        if (i + 1 < ITER)                   // bvr for iter i+1
            w1 = __ldcs(wp + (i + 1) * GSTRIDE);

        float4 c_nxt = c_cur;
        if (i + 1 < ITER)                   // gather for iter i+1 (idx already resident)
            c_nxt = __ldcg(coeff_cache + ci_next);

        float4 r = decode_quarter(w0, c_cur, m0);
        __stcs(op + i * BLOCK, r);

        w0 = w1;
        c_cur = c_nxt;
        ci1 = ci_next; (void)ci1;
    }
}

extern "C" void kernel_launch(void* const* d_in, const int* in_sizes, int n_in,
                              void* d_out, int out_size)
{
    const float4* coeff_cache = (const float4*)d_in[0];  // [65536,4] f32
    const int*    coeff_idx   = (const int*)d_in[1];     // [G] i32
    const int4*   bvr         = (const int4*)d_in[2];    // [G,4] i32
    float4*       out         = (float4*)d_out;          // [8192,8192] f32

    (void)in_sizes; (void)n_in; (void)out_size;

    sbvr_kernel<<<BLOCKS, BLOCK>>>(coeff_cache, coeff_idx, bvr, out);
}